// round 2
// baseline (speedup 1.0000x reference)
#include <cuda_runtime.h>

// Problem constants
#define Bn   2
#define Cc   64
#define Oo   64
#define Gg   16
#define Ee   128
#define Tin  512
#define Wk   7
#define Dd   4
#define Tout 256
#define FO   64
#define PADW 520   // padded smem row: 518 real (512 + 3 + 3), padded to 520

// Scratch
__device__ float  g_Q[Bn * Oo * FO * Tout];   // pooled unnormalized conv [b,o,fo,t]
__device__ float  g_S1[Oo];
__device__ float  g_S2[Oo];
__device__ float2 g_ab[Oo];                    // {a, bias56}

typedef unsigned long long u64;

__device__ __forceinline__ u64 pk2(float lo, float hi) {
    u64 r; asm("mov.b64 %0,{%1,%2};" : "=l"(r) : "f"(lo), "f"(hi)); return r;
}
__device__ __forceinline__ void upk2(u64 v, float& lo, float& hi) {
    asm("mov.b64 {%0,%1},%2;" : "=f"(lo), "=f"(hi) : "l"(v));
}
__device__ __forceinline__ void ffma2(u64& d, u64 a, u64 b) {
    asm("fma.rn.f32x2 %0, %1, %2, %0;" : "+l"(d) : "l"(a), "l"(b));
}

__global__ void zero_kernel() {
    int i = threadIdx.x;
    if (i < Oo) { g_S1[i] = 0.f; g_S2[i] = 0.f; }
}

// Block = (b, g, fo). 2048 blocks, 128 threads.
// Lane mapping: rp = lane&3 handles rows {rp, rp+4}; tc = warp*8 + (lane>>2)
// covers 8 consecutive t outputs for ALL 4 output channels of the group.
// Cross-rp reduction via shfl butterfly; FFMA2 over tap pairs (W padded to 8).
__global__ __launch_bounds__(128) void conv_kernel(const float* __restrict__ x,
                                                   const float* __restrict__ wgt) {
    __shared__ float  xs[8][PADW];      // rows r = f2*4 + d
    __shared__ float2 ws2[8][4][4];     // [r][oc][tap-pair], pair 3 = (w6, 0)
    __shared__ float  bs1[4], bs2[4];

    const int bid = blockIdx.x;
    const int b   = bid >> 10;
    const int g   = (bid >> 6) & 15;
    const int fo  = bid & 63;
    const int tid = threadIdx.x;

    if (tid < 4) { bs1[tid] = 0.f; bs2[tid] = 0.f; }

    // ---- Load padded x rows ----
#pragma unroll
    for (int r = 0; r < 8; r++) {
        int c = g * 4 + (r & 3);
        int f = 2 * fo + (r >> 2);
        const float* xr = &x[((b * Cc + c) * Ee + f) * Tin];
        for (int p = tid; p < PADW; p += 128) {
            int t0 = p - 3;
            xs[r][p] = (t0 >= 0 && t0 < Tin) ? xr[t0] : 0.f;
        }
    }
    // ---- Load weights as tap-pairs (pad w=7 with zero) ----
    {
        int r  = tid >> 4;
        int oc = (tid >> 2) & 3;
        int j  = tid & 3;
        int d  = r & 3;
        int f2 = r >> 2;
        int o  = g * 4 + oc;
        const float* wb = &wgt[((o * Dd + d) * Ee + (2 * fo + f2)) * Wk];
        float lo = wb[2 * j];
        float hi = (j < 3) ? wb[2 * j + 1] : 0.f;
        ws2[r][oc][j] = make_float2(lo, hi);
    }
    __syncthreads();

    const int lane = tid & 31;
    const int warp = tid >> 5;
    const int rp   = lane & 3;             // row-pair id
    const int tc   = warp * 8 + (lane >> 2);
    const int base = tc * 16;              // float offset, 64B aligned

#pragma unroll
    for (int pass = 0; pass < 2; pass++) {
        u64 acc2[2][8];
#pragma unroll
        for (int oo = 0; oo < 2; oo++)
#pragma unroll
            for (int tt = 0; tt < 8; tt++) acc2[oo][tt] = 0ull;

#pragma unroll
        for (int rr = 0; rr < 2; rr++) {
            const int r = rp + rr * 4;
            // Load 22 floats of this thread's window as 11 adjacent pairs
            u64 xp[11];
            const float4* p4 = reinterpret_cast<const float4*>(&xs[r][base]);
#pragma unroll
            for (int k = 0; k < 6; k++) {
                float4 v = p4[k];
                xp[2 * k] = pk2(v.x, v.y);
                if (2 * k + 1 < 11) xp[2 * k + 1] = pk2(v.z, v.w);
            }
#pragma unroll
            for (int oo = 0; oo < 2; oo++) {
                const int oc = pass * 2 + oo;
                const u64* wq = reinterpret_cast<const u64*>(&ws2[r][oc][0]);
                u64 wp0 = wq[0], wp1 = wq[1], wp2 = wq[2], wp3 = wq[3];
#pragma unroll
                for (int tt = 0; tt < 8; tt++) {
                    ffma2(acc2[oo][tt], xp[tt + 0], wp0);
                    ffma2(acc2[oo][tt], xp[tt + 1], wp1);
                    ffma2(acc2[oo][tt], xp[tt + 2], wp2);
                    ffma2(acc2[oo][tt], xp[tt + 3], wp3);
                }
            }
        }
        // ---- Reduce across the 4 rp lanes, then lane rp==oc stores ----
#pragma unroll
        for (int oo = 0; oo < 2; oo++) {
            const int oc = pass * 2 + oo;
            float fin[8];
#pragma unroll
            for (int tt = 0; tt < 8; tt++) {
                float lo, hi;
                upk2(acc2[oo][tt], lo, hi);
                fin[tt] = lo + hi;
                fin[tt] += __shfl_xor_sync(0xffffffffu, fin[tt], 1);
                fin[tt] += __shfl_xor_sync(0xffffffffu, fin[tt], 2);
            }
            if (rp == oc) {
                int qb = ((b * Oo + g * 4 + oc) * FO + fo) * Tout + tc * 8;
                *reinterpret_cast<float4*>(&g_Q[qb]) =
                    make_float4(fin[0], fin[1], fin[2], fin[3]);
                *reinterpret_cast<float4*>(&g_Q[qb + 4]) =
                    make_float4(fin[4], fin[5], fin[6], fin[7]);
            }
        }
    }

    // ---- Channel-stat parity sums (unchanged math) ----
#pragma unroll
    for (int rr2 = warp; rr2 < 8; rr2 += 4) {
        float pe = 0.f, po = 0.f, pe2 = 0.f, po2 = 0.f;
        const float2* xr2 = reinterpret_cast<const float2*>(&xs[rr2][0]);
        for (int m = lane; m < 259; m += 32) {
            float2 v = xr2[m];
            pe += v.x; pe2 += v.x * v.x;
            po += v.y; po2 += v.y * v.y;
        }
#pragma unroll
        for (int off = 16; off > 0; off >>= 1) {
            pe  += __shfl_xor_sync(0xffffffffu, pe,  off);
            po  += __shfl_xor_sync(0xffffffffu, po,  off);
            pe2 += __shfl_xor_sync(0xffffffffu, pe2, off);
            po2 += __shfl_xor_sync(0xffffffffu, po2, off);
        }
        if (lane == 0) {
            float b512 = xs[rr2][512], b513 = xs[rr2][513], b514 = xs[rr2][514];
            float b3 = xs[rr2][3], b4 = xs[rr2][4];
            float s1[7], s2[7];
            s1[0] = pe - b512 - b514;  s2[0] = pe2 - b512 * b512 - b514 * b514;
            s1[1] = po - b513;         s2[1] = po2 - b513 * b513;
            s1[2] = pe - b514;         s2[2] = pe2 - b514 * b514;
            s1[3] = po;                s2[3] = po2;
            s1[4] = pe;                s2[4] = pe2;
            s1[5] = po - b3;           s2[5] = po2 - b3 * b3;
            s1[6] = pe - b4;           s2[6] = pe2 - b4 * b4;
#pragma unroll
            for (int occ = 0; occ < 4; occ++) {
                float c1 = 0.f, c2 = 0.f;
#pragma unroll
                for (int w = 0; w < 7; w++) {
                    float wv = (w & 1) ? ws2[rr2][occ][w >> 1].y
                                       : ws2[rr2][occ][w >> 1].x;
                    c1 = fmaf(wv, s1[w], c1);
                    c2 = fmaf(wv * wv, s2[w], c2);
                }
                atomicAdd(&bs1[occ], c1);
                atomicAdd(&bs2[occ], c2);
            }
        }
    }
    __syncthreads();
    if (tid < 4) {
        atomicAdd(&g_S1[g * 4 + tid], bs1[tid]);
        atomicAdd(&g_S2[g * 4 + tid], bs2[tid]);
    }
}

__global__ void finalize_kernel(const float* __restrict__ gamma,
                                const float* __restrict__ beta) {
    int o = threadIdx.x;
    if (o < Oo) {
        const float M = 1835008.f;  // B*D*E*t*W
        float mean = g_S1[o] / M;
        float var  = g_S2[o] / M - mean * mean;
        float a    = gamma[o] * rsqrtf(var + 1e-5f);
        float bias = 56.f * (beta[o] - mean * a);
        g_ab[o] = make_float2(a, bias);
    }
}

// out = leaky(a[o]*Q + bias56[o]); 4 independent float4 per thread for ILP.
// 524288 float4 total -> 512 blocks x 256 threads x 4.
__global__ __launch_bounds__(256) void apply_kernel(float* __restrict__ out) {
    int base = blockIdx.x * 1024 + threadIdx.x;
    float4 q[4];
    int idx[4];
#pragma unroll
    for (int k = 0; k < 4; k++) {
        idx[k] = base + k * 256;
        q[k] = reinterpret_cast<const float4*>(g_Q)[idx[k]];
    }
#pragma unroll
    for (int k = 0; k < 4; k++) {
        int o = (idx[k] >> 12) & 63;
        float2 ab = g_ab[o];
        float4 r;
        r.x = fmaf(ab.x, q[k].x, ab.y);
        r.y = fmaf(ab.x, q[k].y, ab.y);
        r.z = fmaf(ab.x, q[k].z, ab.y);
        r.w = fmaf(ab.x, q[k].w, ab.y);
        r.x = (r.x >= 0.f) ? r.x : 0.01f * r.x;
        r.y = (r.y >= 0.f) ? r.y : 0.01f * r.y;
        r.z = (r.z >= 0.f) ? r.z : 0.01f * r.z;
        r.w = (r.w >= 0.f) ? r.w : 0.01f * r.w;
        reinterpret_cast<float4*>(out)[idx[k]] = r;
    }
}

extern "C" void kernel_launch(void* const* d_in, const int* in_sizes, int n_in,
                              void* d_out, int out_size) {
    const float* x     = (const float*)d_in[0];
    const float* wgt   = (const float*)d_in[1];
    const float* gamma = (const float*)d_in[2];
    const float* beta  = (const float*)d_in[3];

    zero_kernel<<<1, 64>>>();
    conv_kernel<<<2048, 128>>>(x, wgt);
    finalize_kernel<<<1, 64>>>(gamma, beta);
    apply_kernel<<<512, 256>>>((float*)d_out);
}

// round 3
// speedup vs baseline: 1.6504x; 1.6504x over previous
#include <cuda_runtime.h>

// Problem constants
#define Bn   2
#define Cc   64
#define Oo   64
#define Gg   16
#define Ee   128
#define Tin  512
#define Wk   7
#define Dd   4
#define Tout 256
#define FO   64
#define PADW 520

// Per-block BN-stat partials: [o][j], j = b*64 + d*16 + fc  (2*4*16 = 128 slots)
__device__ float g_part1[Oo][128];
__device__ float g_part2[Oo][128];

// ---------------------------------------------------------------------------
// Stats kernel: grid (b, c, fc) = 2*64*16 = 2048 blocks, 256 threads (8 warps).
// Warp w handles row f = fc*8 + w. Computes per-row parity sums of x and x^2,
// converts to per-tap sums s1[w]/s2[w] via boundary corrections, dots with
// weights for the 4 output channels of the group, accumulates per-block.
// ---------------------------------------------------------------------------
__global__ __launch_bounds__(256) void stats_kernel(const float* __restrict__ x,
                                                    const float* __restrict__ wgt) {
    __shared__ float s_p1[4], s_p2[4];

    const int bid = blockIdx.x;
    const int b   = bid >> 10;
    const int c   = (bid >> 4) & 63;
    const int fc  = bid & 15;
    const int tid = threadIdx.x;
    const int warp = tid >> 5;
    const int lane = tid & 31;

    if (tid < 4) { s_p1[tid] = 0.f; s_p2[tid] = 0.f; }
    __syncthreads();

    const int f = fc * 8 + warp;
    const float4* row = reinterpret_cast<const float4*>(
        &x[(((b * Cc + c) * Ee) + f) * Tin]);

    // so: sum over odd t, se: sum over even t (t parity within float4: x,z even; y,w odd)
    float so = 0.f, se = 0.f, so2 = 0.f, se2 = 0.f;
    float4 v0, v3;
#pragma unroll
    for (int q = 0; q < 4; q++) {
        float4 v = row[lane + 32 * q];
        if (q == 0) v0 = v;
        if (q == 3) v3 = v;
        se += v.x + v.z;  se2 += v.x * v.x + v.z * v.z;
        so += v.y + v.w;  so2 += v.y * v.y + v.w * v.w;
    }
#pragma unroll
    for (int off = 16; off > 0; off >>= 1) {
        so  += __shfl_xor_sync(0xffffffffu, so,  off);
        se  += __shfl_xor_sync(0xffffffffu, se,  off);
        so2 += __shfl_xor_sync(0xffffffffu, so2, off);
        se2 += __shfl_xor_sync(0xffffffffu, se2, off);
    }
    float x0   = __shfl_sync(0xffffffffu, v0.x, 0);
    float x1   = __shfl_sync(0xffffffffu, v0.y, 0);
    float x509 = __shfl_sync(0xffffffffu, v3.y, 31);
    float x510 = __shfl_sync(0xffffffffu, v3.z, 31);
    float x511 = __shfl_sync(0xffffffffu, v3.w, 31);

    if (lane < 4) {
        // per-tap sums: s1[w] = sum_{t'=0..255} x_pad[2t'+w], pad=3
        float s1[7], s2[7];
        s1[0] = so - x509 - x511;  s2[0] = so2 - x509 * x509 - x511 * x511;
        s1[1] = se - x510;         s2[1] = se2 - x510 * x510;
        s1[2] = so - x511;         s2[2] = so2 - x511 * x511;
        s1[3] = se;                s2[3] = se2;
        s1[4] = so;                s2[4] = so2;
        s1[5] = se - x0;           s2[5] = se2 - x0 * x0;
        s1[6] = so - x1;           s2[6] = so2 - x1 * x1;

        const int g = c >> 2, d = c & 3;
        const int o = g * 4 + lane;
        const float* wp = &wgt[((o * Dd + d) * Ee + f) * Wk];
        float c1 = 0.f, c2 = 0.f;
#pragma unroll
        for (int w = 0; w < 7; w++) {
            float wv = wp[w];
            c1 = fmaf(wv, s1[w], c1);
            c2 = fmaf(wv * wv, s2[w], c2);
        }
        atomicAdd(&s_p1[lane], c1);
        atomicAdd(&s_p2[lane], c2);
    }
    __syncthreads();
    if (tid < 4) {
        const int g = c >> 2, d = c & 3;
        const int j = b * 64 + d * 16 + fc;
        g_part1[g * 4 + tid][j] = s_p1[tid];
        g_part2[g * 4 + tid][j] = s_p2[tid];
    }
}

// ---------------------------------------------------------------------------
// Conv + BN-affine + LeakyReLU, fused. Block = (b, g, fo), 2048 blocks, 128 thr.
// Prologue reduces g_part into a/bias for the block's 4 channels (overlapped
// with the smem x fill). Main loop = Round-1 proven FFMA core. Writes out
// directly.
// ---------------------------------------------------------------------------
__global__ __launch_bounds__(128) void conv_kernel(const float* __restrict__ x,
                                                   const float* __restrict__ wgt,
                                                   const float* __restrict__ gamma,
                                                   const float* __restrict__ beta,
                                                   float* __restrict__ out) {
    __shared__ float  xs[8][PADW];
    __shared__ float  ws[8][4][7];
    __shared__ float  sa1[4], sa2[4];
    __shared__ float2 s_ab[4];

    const int bid = blockIdx.x;
    const int b   = bid >> 10;
    const int g   = (bid >> 6) & 15;
    const int fo  = bid & 63;
    const int tid = threadIdx.x;

    if (tid < 4) { sa1[tid] = 0.f; sa2[tid] = 0.f; }
    __syncthreads();

    // ---- x rows into smem ----
    for (int idx = tid; idx < 8 * PADW; idx += 128) {
        int r = idx / PADW;
        int p = idx - r * PADW;
        int c = g * 4 + (r & 3);
        int f = 2 * fo + (r >> 2);
        float v = 0.f;
        int t0 = p - 3;
        if (t0 >= 0 && t0 < Tin)
            v = x[((b * Cc + c) * Ee + f) * Tin + t0];
        xs[r][p] = v;
    }
    // ---- weights ----
    for (int j = tid; j < 224; j += 128) {
        int r   = j / 28;
        int rem = j - r * 28;
        int oc  = rem / 7;
        int w   = rem - oc * 7;
        int d   = r & 3;
        int f2  = r >> 2;
        int o   = g * 4 + oc;
        ws[r][oc][w] = wgt[((o * Dd + d) * Ee + (2 * fo + f2)) * Wk + w];
    }
    // ---- reduce stat partials for this group's 4 channels ----
    {
        int oc = tid & 3;
        int k  = tid >> 2;
        int o  = g * 4 + oc;
        float p1 = 0.f, p2 = 0.f;
#pragma unroll
        for (int kk = 0; kk < 4; kk++) {
            p1 += g_part1[o][k + 32 * kk];
            p2 += g_part2[o][k + 32 * kk];
        }
        atomicAdd(&sa1[oc], p1);
        atomicAdd(&sa2[oc], p2);
    }
    __syncthreads();
    if (tid < 4) {
        const float M = 1835008.f;  // B*D*E*t*W
        int o = g * 4 + tid;
        float mean = sa1[tid] / M;
        float var  = sa2[tid] / M - mean * mean;
        float a    = gamma[o] * rsqrtf(var + 1e-5f);
        s_ab[tid]  = make_float2(a, 56.f * (beta[o] - mean * a));
    }
    __syncthreads();

    // ---- Main conv: Round-1 core ----
    const int tc   = tid >> 2;
    const int oc   = tid & 3;
    const int base = tc * 16;

    float acc[8];
#pragma unroll
    for (int i = 0; i < 8; i++) acc[i] = 0.f;

#pragma unroll
    for (int r = 0; r < 8; r++) {
        float xw[24];
        const float4* rp = reinterpret_cast<const float4*>(&xs[r][base]);
#pragma unroll
        for (int j = 0; j < 6; j++) {
            float4 v = rp[j];
            xw[4 * j + 0] = v.x; xw[4 * j + 1] = v.y;
            xw[4 * j + 2] = v.z; xw[4 * j + 3] = v.w;
        }
        float wt[7];
#pragma unroll
        for (int w = 0; w < 7; w++) wt[w] = ws[r][oc][w];
#pragma unroll
        for (int tt = 0; tt < 8; tt++)
#pragma unroll
            for (int w = 0; w < 7; w++)
                acc[tt] = fmaf(xw[2 * tt + w], wt[w], acc[tt]);
    }

    // ---- affine + leaky + store directly to out ----
    {
        float2 ab = s_ab[oc];
        float r0[8];
#pragma unroll
        for (int tt = 0; tt < 8; tt++) {
            float v = fmaf(ab.x, acc[tt], ab.y);
            r0[tt] = (v >= 0.f) ? v : 0.01f * v;
        }
        int o  = g * 4 + oc;
        int ob = ((b * Oo + o) * FO + fo) * Tout + tc * 8;
        *reinterpret_cast<float4*>(&out[ob])     = make_float4(r0[0], r0[1], r0[2], r0[3]);
        *reinterpret_cast<float4*>(&out[ob + 4]) = make_float4(r0[4], r0[5], r0[6], r0[7]);
    }
}

extern "C" void kernel_launch(void* const* d_in, const int* in_sizes, int n_in,
                              void* d_out, int out_size) {
    const float* x     = (const float*)d_in[0];
    const float* wgt   = (const float*)d_in[1];
    const float* gamma = (const float*)d_in[2];
    const float* beta  = (const float*)d_in[3];

    stats_kernel<<<2048, 256>>>(x, wgt);
    conv_kernel<<<2048, 128>>>(x, wgt, gamma, beta, (float*)d_out);
}

// round 4
// speedup vs baseline: 2.0531x; 1.2440x over previous
#include <cuda_runtime.h>

// Problem constants
#define Bn   2
#define Cc   64
#define Oo   64
#define Gg   16
#define Ee   128
#define Tin  512
#define Wk   7
#define Dd   4
#define Tout 256
#define FO   64
#define PER  264   // padded de-interleaved row length (floats)

// Per-block BN-stat partials: [o][j], j = b*64 + d*16 + fc  (128 slots)
__device__ float g_part1[Oo][128];
__device__ float g_part2[Oo][128];

// ---------------------------------------------------------------------------
// Stats kernel (validated in R3): grid (b, c, fc) = 2048 blocks, 256 threads.
// ---------------------------------------------------------------------------
__global__ __launch_bounds__(256) void stats_kernel(const float* __restrict__ x,
                                                    const float* __restrict__ wgt) {
    __shared__ float s_p1[4], s_p2[4];

    const int bid = blockIdx.x;
    const int b   = bid >> 10;
    const int c   = (bid >> 4) & 63;
    const int fc  = bid & 15;
    const int tid = threadIdx.x;
    const int warp = tid >> 5;
    const int lane = tid & 31;

    if (tid < 4) { s_p1[tid] = 0.f; s_p2[tid] = 0.f; }
    __syncthreads();

    const int f = fc * 8 + warp;
    const float4* row = reinterpret_cast<const float4*>(
        &x[(((b * Cc + c) * Ee) + f) * Tin]);

    float so = 0.f, se = 0.f, so2 = 0.f, se2 = 0.f;
    float4 v0, v3;
#pragma unroll
    for (int q = 0; q < 4; q++) {
        float4 v = row[lane + 32 * q];
        if (q == 0) v0 = v;
        if (q == 3) v3 = v;
        se += v.x + v.z;  se2 += v.x * v.x + v.z * v.z;
        so += v.y + v.w;  so2 += v.y * v.y + v.w * v.w;
    }
#pragma unroll
    for (int off = 16; off > 0; off >>= 1) {
        so  += __shfl_xor_sync(0xffffffffu, so,  off);
        se  += __shfl_xor_sync(0xffffffffu, se,  off);
        so2 += __shfl_xor_sync(0xffffffffu, so2, off);
        se2 += __shfl_xor_sync(0xffffffffu, se2, off);
    }
    float x0   = __shfl_sync(0xffffffffu, v0.x, 0);
    float x1   = __shfl_sync(0xffffffffu, v0.y, 0);
    float x509 = __shfl_sync(0xffffffffu, v3.y, 31);
    float x510 = __shfl_sync(0xffffffffu, v3.z, 31);
    float x511 = __shfl_sync(0xffffffffu, v3.w, 31);

    if (lane < 4) {
        float s1[7], s2[7];
        s1[0] = so - x509 - x511;  s2[0] = so2 - x509 * x509 - x511 * x511;
        s1[1] = se - x510;         s2[1] = se2 - x510 * x510;
        s1[2] = so - x511;         s2[2] = so2 - x511 * x511;
        s1[3] = se;                s2[3] = se2;
        s1[4] = so;                s2[4] = so2;
        s1[5] = se - x0;           s2[5] = se2 - x0 * x0;
        s1[6] = so - x1;           s2[6] = so2 - x1 * x1;

        const int g = c >> 2, d = c & 3;
        const int o = g * 4 + lane;
        const float* wp = &wgt[((o * Dd + d) * Ee + f) * Wk];
        float c1 = 0.f, c2 = 0.f;
#pragma unroll
        for (int w = 0; w < 7; w++) {
            float wv = wp[w];
            c1 = fmaf(wv, s1[w], c1);
            c2 = fmaf(wv * wv, s2[w], c2);
        }
        atomicAdd(&s_p1[lane], c1);
        atomicAdd(&s_p2[lane], c2);
    }
    __syncthreads();
    if (tid < 4) {
        const int g = c >> 2, d = c & 3;
        const int j = b * 64 + d * 16 + fc;
        g_part1[g * 4 + tid][j] = s_p1[tid];
        g_part2[g * 4 + tid][j] = s_p2[tid];
    }
}

// ---------------------------------------------------------------------------
// Fused conv + BN-affine + LeakyReLU. Block = (b, g, fo), 2048 blocks, 256 thr.
// De-interleaved smem:  pe[r][i] = pad[2i],  pos[r][i] = pad[2i-1]  (pad = x
// zero-padded by 3).  out[t] = sum_u w[2u]*pe[t+u] + sum_u w[2u+1]*pos[t+u+1].
// Thread = (oc = lane&3, tc = warp*8 + lane>>2): 4 consecutive t per thread.
// All window LDS.128 are conflict-free (contiguous 128B/warp + 4x broadcast).
// ---------------------------------------------------------------------------
__global__ __launch_bounds__(256) void conv_kernel(const float* __restrict__ x,
                                                   const float* __restrict__ wgt,
                                                   const float* __restrict__ gamma,
                                                   const float* __restrict__ beta,
                                                   float* __restrict__ out) {
    __shared__ alignas(16) float pe[8][PER];
    __shared__ alignas(16) float pos[8][PER];
    __shared__ alignas(16) float ws[8][4][8];   // taps padded: [w0..w6, 0]
    __shared__ float2 s_ab[4];

    const int bid  = blockIdx.x;
    const int b    = bid >> 10;
    const int g    = (bid >> 6) & 15;
    const int fo   = bid & 63;
    const int tid  = threadIdx.x;
    const int lane = tid & 31;
    const int warp = tid >> 5;

    // ---- zero boundary slots: indices {0,1,258..263} of each pe/pos row ----
    if (tid < 128) {
        int r  = tid >> 4;
        int s  = tid & 15;
        int ss = s & 7;
        int idx = (ss < 2) ? ss : (256 + ss);
        if (s < 8) pe[r][idx] = 0.f; else pos[r][idx] = 0.f;
    }

    // ---- de-interleaving x fill: 4 float4 LDGs per thread ----
#pragma unroll
    for (int k = 0; k < 4; k++) {
        int idx = tid + 256 * k;          // 0..1023
        int r   = idx >> 7;               // 0..7
        int i   = idx & 127;              // float4 index within row
        int c   = g * 4 + (r & 3);
        int f   = 2 * fo + (r >> 2);
        float4 v = reinterpret_cast<const float4*>(
            &x[((b * Cc + c) * Ee + f) * Tin])[i];
        // pe[u]=pad[2u]=x[2u-3]: x[4i+1]->u=2i+2, x[4i+3]->u=2i+3
        *reinterpret_cast<float2*>(&pe[r][2 * i + 2])  = make_float2(v.y, v.w);
        // pos[u]=pad[2u-1]=x[2u-4]: x[4i]->u=2i+2, x[4i+2]->u=2i+3
        *reinterpret_cast<float2*>(&pos[r][2 * i + 2]) = make_float2(v.x, v.z);
    }

    // ---- weights: one slot per thread (256 = 8r * 4oc * 8w) ----
    {
        int r  = tid >> 5;
        int oc = (tid >> 3) & 3;
        int w  = tid & 7;
        int d  = r & 3;
        int f2 = r >> 2;
        int o  = g * 4 + oc;
        ws[r][oc][w] = (w < 7)
            ? wgt[((o * Dd + d) * Ee + (2 * fo + f2)) * Wk + w] : 0.f;
    }

    // ---- warp 0: reduce 128 stat partials per channel -> a / bias ----
    if (warp == 0) {
        int ocr = lane >> 3;              // 0..3
        int j   = lane & 7;
        int o   = g * 4 + ocr;
        float p1 = 0.f, p2 = 0.f;
#pragma unroll
        for (int m = 0; m < 16; m++) {
            p1 += g_part1[o][j + 8 * m];
            p2 += g_part2[o][j + 8 * m];
        }
#pragma unroll
        for (int off = 4; off > 0; off >>= 1) {
            p1 += __shfl_xor_sync(0xffffffffu, p1, off);
            p2 += __shfl_xor_sync(0xffffffffu, p2, off);
        }
        if (j == 0) {
            const float M = 1835008.f;    // B*D*E*t*W
            float mean = p1 / M;
            float var  = p2 / M - mean * mean;
            float a    = gamma[o] * rsqrtf(var + 1e-5f);
            s_ab[ocr]  = make_float2(a, 56.f * (beta[o] - mean * a));
        }
    }
    __syncthreads();

    // ---- main conv: 4 outputs per thread, conflict-free windows ----
    const int oc = lane & 3;
    const int tc = warp * 8 + (lane >> 2);        // 0..63; t = 4*tc..4*tc+3
    float a0 = 0.f, a1 = 0.f, a2 = 0.f, a3 = 0.f;

#pragma unroll
    for (int r = 0; r < 8; r++) {
        const float4* per = reinterpret_cast<const float4*>(pe[r]);
        const float4* por = reinterpret_cast<const float4*>(pos[r]);
        float4 e0 = per[tc], e1 = per[tc + 1];
        float4 s0 = por[tc], s1 = por[tc + 1];
        float4 wA = *reinterpret_cast<const float4*>(&ws[r][oc][0]); // w0..w3
        float4 wB = *reinterpret_cast<const float4*>(&ws[r][oc][4]); // w4,w5,w6,0

        // even taps: w0,w2,w4,w6 = wA.x, wA.z, wB.x, wB.z over e[j..j+3]
        a0 = fmaf(wA.x, e0.x, a0); a0 = fmaf(wA.z, e0.y, a0);
        a0 = fmaf(wB.x, e0.z, a0); a0 = fmaf(wB.z, e0.w, a0);
        a1 = fmaf(wA.x, e0.y, a1); a1 = fmaf(wA.z, e0.z, a1);
        a1 = fmaf(wB.x, e0.w, a1); a1 = fmaf(wB.z, e1.x, a1);
        a2 = fmaf(wA.x, e0.z, a2); a2 = fmaf(wA.z, e0.w, a2);
        a2 = fmaf(wB.x, e1.x, a2); a2 = fmaf(wB.z, e1.y, a2);
        a3 = fmaf(wA.x, e0.w, a3); a3 = fmaf(wA.z, e1.x, a3);
        a3 = fmaf(wB.x, e1.y, a3); a3 = fmaf(wB.z, e1.z, a3);
        // odd taps: w1,w3,w5 = wA.y, wA.w, wB.y over s[j+1..j+3]
        a0 = fmaf(wA.y, s0.y, a0); a0 = fmaf(wA.w, s0.z, a0);
        a0 = fmaf(wB.y, s0.w, a0);
        a1 = fmaf(wA.y, s0.z, a1); a1 = fmaf(wA.w, s0.w, a1);
        a1 = fmaf(wB.y, s1.x, a1);
        a2 = fmaf(wA.y, s0.w, a2); a2 = fmaf(wA.w, s1.x, a2);
        a2 = fmaf(wB.y, s1.y, a2);
        a3 = fmaf(wA.y, s1.x, a3); a3 = fmaf(wA.w, s1.y, a3);
        a3 = fmaf(wB.y, s1.z, a3);
    }

    // ---- affine + leaky + coalesced STG.128 ----
    {
        float2 ab = s_ab[oc];
        float4 r4;
        r4.x = fmaf(ab.x, a0, ab.y);
        r4.y = fmaf(ab.x, a1, ab.y);
        r4.z = fmaf(ab.x, a2, ab.y);
        r4.w = fmaf(ab.x, a3, ab.y);
        r4.x = (r4.x >= 0.f) ? r4.x : 0.01f * r4.x;
        r4.y = (r4.y >= 0.f) ? r4.y : 0.01f * r4.y;
        r4.z = (r4.z >= 0.f) ? r4.z : 0.01f * r4.z;
        r4.w = (r4.w >= 0.f) ? r4.w : 0.01f * r4.w;
        int o  = g * 4 + oc;
        int ob = ((b * Oo + o) * FO + fo) * Tout + 4 * tc;
        *reinterpret_cast<float4*>(&out[ob]) = r4;
    }
}

extern "C" void kernel_launch(void* const* d_in, const int* in_sizes, int n_in,
                              void* d_out, int out_size) {
    const float* x     = (const float*)d_in[0];
    const float* wgt   = (const float*)d_in[1];
    const float* gamma = (const float*)d_in[2];
    const float* beta  = (const float*)d_in[3];

    stats_kernel<<<2048, 256>>>(x, wgt);
    conv_kernel<<<2048, 256>>>(x, wgt, gamma, beta, (float*)d_out);
}

// round 5
// speedup vs baseline: 2.0741x; 1.0102x over previous
#include <cuda_runtime.h>

// Problem constants
#define Bn   2
#define Cc   64
#define Oo   64
#define Gg   16
#define Ee   128
#define Tin  512
#define Wk   7
#define Dd   4
#define Tout 256
#define FO   64
#define PER  264   // padded de-interleaved row length (floats)

// Per-block BN-stat partials: [o][j], j = b*64 + d*16 + fc  (128 slots)
__device__ float  g_part1[Oo][128];
__device__ float  g_part2[Oo][128];
__device__ float2 g_ab[Oo];           // {a, bias56}

// ---------------------------------------------------------------------------
// Stats kernel (validated): grid (b, c, fc) = 2048 blocks, 256 threads.
// ---------------------------------------------------------------------------
__global__ __launch_bounds__(256) void stats_kernel(const float* __restrict__ x,
                                                    const float* __restrict__ wgt) {
    __shared__ float s_p1[4], s_p2[4];

    const int bid = blockIdx.x;
    const int b   = bid >> 10;
    const int c   = (bid >> 4) & 63;
    const int fc  = bid & 15;
    const int tid = threadIdx.x;
    const int warp = tid >> 5;
    const int lane = tid & 31;

    if (tid < 4) { s_p1[tid] = 0.f; s_p2[tid] = 0.f; }
    __syncthreads();

    const int f = fc * 8 + warp;
    const float4* row = reinterpret_cast<const float4*>(
        &x[(((b * Cc + c) * Ee) + f) * Tin]);

    float so = 0.f, se = 0.f, so2 = 0.f, se2 = 0.f;
    float4 v0, v3;
#pragma unroll
    for (int q = 0; q < 4; q++) {
        float4 v = row[lane + 32 * q];
        if (q == 0) v0 = v;
        if (q == 3) v3 = v;
        se += v.x + v.z;  se2 += v.x * v.x + v.z * v.z;
        so += v.y + v.w;  so2 += v.y * v.y + v.w * v.w;
    }
#pragma unroll
    for (int off = 16; off > 0; off >>= 1) {
        so  += __shfl_xor_sync(0xffffffffu, so,  off);
        se  += __shfl_xor_sync(0xffffffffu, se,  off);
        so2 += __shfl_xor_sync(0xffffffffu, so2, off);
        se2 += __shfl_xor_sync(0xffffffffu, se2, off);
    }
    float x0   = __shfl_sync(0xffffffffu, v0.x, 0);
    float x1   = __shfl_sync(0xffffffffu, v0.y, 0);
    float x509 = __shfl_sync(0xffffffffu, v3.y, 31);
    float x510 = __shfl_sync(0xffffffffu, v3.z, 31);
    float x511 = __shfl_sync(0xffffffffu, v3.w, 31);

    if (lane < 4) {
        float s1[7], s2[7];
        s1[0] = so - x509 - x511;  s2[0] = so2 - x509 * x509 - x511 * x511;
        s1[1] = se - x510;         s2[1] = se2 - x510 * x510;
        s1[2] = so - x511;         s2[2] = so2 - x511 * x511;
        s1[3] = se;                s2[3] = se2;
        s1[4] = so;                s2[4] = so2;
        s1[5] = se - x0;           s2[5] = se2 - x0 * x0;
        s1[6] = so - x1;           s2[6] = so2 - x1 * x1;

        const int g = c >> 2, d = c & 3;
        const int o = g * 4 + lane;
        const float* wp = &wgt[((o * Dd + d) * Ee + f) * Wk];
        float c1 = 0.f, c2 = 0.f;
#pragma unroll
        for (int w = 0; w < 7; w++) {
            float wv = wp[w];
            c1 = fmaf(wv, s1[w], c1);
            c2 = fmaf(wv * wv, s2[w], c2);
        }
        atomicAdd(&s_p1[lane], c1);
        atomicAdd(&s_p2[lane], c2);
    }
    __syncthreads();
    if (tid < 4) {
        const int g = c >> 2, d = c & 3;
        const int j = b * 64 + d * 16 + fc;
        g_part1[g * 4 + tid][j] = s_p1[tid];
        g_part2[g * 4 + tid][j] = s_p2[tid];
    }
}

// ---------------------------------------------------------------------------
// Finalize: 1 block, 256 threads. Thread (o = tid>>2, q = tid&3) reduces 32
// partials of each array (8 float4 loads), combines via shfl, writes g_ab.
// ---------------------------------------------------------------------------
__global__ __launch_bounds__(256) void finalize_kernel(const float* __restrict__ gamma,
                                                       const float* __restrict__ beta) {
    const int tid = threadIdx.x;
    const int o = tid >> 2, q = tid & 3;
    const float4* p1v = reinterpret_cast<const float4*>(&g_part1[o][q * 32]);
    const float4* p2v = reinterpret_cast<const float4*>(&g_part2[o][q * 32]);
    float p1 = 0.f, p2 = 0.f;
#pragma unroll
    for (int k = 0; k < 8; k++) {
        float4 a = p1v[k], b = p2v[k];
        p1 += (a.x + a.y) + (a.z + a.w);
        p2 += (b.x + b.y) + (b.z + b.w);
    }
#pragma unroll
    for (int off = 1; off < 4; off <<= 1) {
        p1 += __shfl_xor_sync(0xffffffffu, p1, off);
        p2 += __shfl_xor_sync(0xffffffffu, p2, off);
    }
    if (q == 0) {
        const float M = 1835008.f;   // B*D*E*t*W
        float mean = p1 / M;
        float var  = p2 / M - mean * mean;
        float a    = gamma[o] * rsqrtf(var + 1e-5f);
        g_ab[o] = make_float2(a, 56.f * (beta[o] - mean * a));
    }
}

// ---------------------------------------------------------------------------
// Fused conv + BN-affine + LeakyReLU. Block = (b, g, fo), 2048 blocks, 128 thr.
// De-interleaved smem: pe[u]=pad[2u], pos[u]=pad[2u-1].
// Thread = (oc = lane&3, tc = warp*8 + lane>>2): 8 consecutive t per thread.
// Per row: 6 window LDS.128 + 2 weight LDS.128 for 8 outputs (1.0 LDS/output).
// ---------------------------------------------------------------------------
__global__ __launch_bounds__(128) void conv_kernel(const float* __restrict__ x,
                                                   const float* __restrict__ wgt,
                                                   float* __restrict__ out) {
    __shared__ alignas(16) float pe[8][PER];
    __shared__ alignas(16) float pos[8][PER];
    __shared__ alignas(16) float ws[8][4][8];   // [w0..w6, 0]

    const int bid  = blockIdx.x;
    const int b    = bid >> 10;
    const int g    = (bid >> 6) & 15;
    const int fo   = bid & 63;
    const int tid  = threadIdx.x;
    const int lane = tid & 31;
    const int warp = tid >> 5;
    const int oc   = lane & 3;
    const int tc   = warp * 8 + (lane >> 2);   // 0..31; outputs t = 8tc..8tc+7

    // BN affine coefficients (consumed only in epilogue; latency hidden)
    const float2 ab = g_ab[g * 4 + oc];

    // ---- zero boundary slots {0,1,258..263} of each pe/pos row ----
    {
        int r  = tid >> 4;
        int s  = tid & 15;
        int ss = s & 7;
        int idx = (ss < 2) ? ss : (256 + ss);
        if (s < 8) pe[r][idx] = 0.f; else pos[r][idx] = 0.f;
    }

    // ---- de-interleaving fill: row r = k, float4 i = tid (coalesced) ----
#pragma unroll
    for (int k = 0; k < 8; k++) {
        const int c = g * 4 + (k & 3);
        const int f = 2 * fo + (k >> 2);
        float4 v = reinterpret_cast<const float4*>(
            &x[((b * Cc + c) * Ee + f) * Tin])[tid];
        *reinterpret_cast<float2*>(&pe[k][2 * tid + 2])  = make_float2(v.y, v.w);
        *reinterpret_cast<float2*>(&pos[k][2 * tid + 2]) = make_float2(v.x, v.z);
    }

    // ---- weights: 2 slots per thread (256 = 8r * 4oc * 8w) ----
#pragma unroll
    for (int m = 0; m < 2; m++) {
        int j  = tid + 128 * m;
        int r  = j >> 5;
        int o2 = (j >> 3) & 3;
        int w  = j & 7;
        int d  = r & 3;
        int f2 = r >> 2;
        ws[r][o2][w] = (w < 7)
            ? wgt[(((g * 4 + o2) * Dd + d) * Ee + (2 * fo + f2)) * Wk + w] : 0.f;
    }
    __syncthreads();

    // ---- main conv: 8 outputs per thread ----
    float acc[8];
#pragma unroll
    for (int j = 0; j < 8; j++) acc[j] = 0.f;

#pragma unroll
    for (int r = 0; r < 8; r++) {
        const float4* pe4  = reinterpret_cast<const float4*>(pe[r]);
        const float4* pos4 = reinterpret_cast<const float4*>(pos[r]);
        float E[12], S[12];
        *reinterpret_cast<float4*>(&E[0]) = pe4[2 * tc];
        *reinterpret_cast<float4*>(&E[4]) = pe4[2 * tc + 1];
        *reinterpret_cast<float4*>(&E[8]) = pe4[2 * tc + 2];
        *reinterpret_cast<float4*>(&S[0]) = pos4[2 * tc];
        *reinterpret_cast<float4*>(&S[4]) = pos4[2 * tc + 1];
        *reinterpret_cast<float4*>(&S[8]) = pos4[2 * tc + 2];
        float4 wA = *reinterpret_cast<const float4*>(&ws[r][oc][0]); // w0..w3
        float4 wB = *reinterpret_cast<const float4*>(&ws[r][oc][4]); // w4,w5,w6,0
#pragma unroll
        for (int j = 0; j < 8; j++) {
            acc[j] = fmaf(wA.x, E[j],     acc[j]);
            acc[j] = fmaf(wA.y, S[j + 1], acc[j]);
            acc[j] = fmaf(wA.z, E[j + 1], acc[j]);
            acc[j] = fmaf(wA.w, S[j + 2], acc[j]);
            acc[j] = fmaf(wB.x, E[j + 2], acc[j]);
            acc[j] = fmaf(wB.y, S[j + 3], acc[j]);
            acc[j] = fmaf(wB.z, E[j + 3], acc[j]);
        }
    }

    // ---- affine + leaky + two coalesced STG.128 ----
    {
        float r0[8];
#pragma unroll
        for (int j = 0; j < 8; j++) {
            float v = fmaf(ab.x, acc[j], ab.y);
            r0[j] = (v >= 0.f) ? v : 0.01f * v;
        }
        int ob = ((b * Oo + g * 4 + oc) * FO + fo) * Tout + 8 * tc;
        *reinterpret_cast<float4*>(&out[ob])     = make_float4(r0[0], r0[1], r0[2], r0[3]);
        *reinterpret_cast<float4*>(&out[ob + 4]) = make_float4(r0[4], r0[5], r0[6], r0[7]);
    }
}

extern "C" void kernel_launch(void* const* d_in, const int* in_sizes, int n_in,
                              void* d_out, int out_size) {
    const float* x     = (const float*)d_in[0];
    const float* wgt   = (const float*)d_in[1];
    const float* gamma = (const float*)d_in[2];
    const float* beta  = (const float*)d_in[3];

    stats_kernel<<<2048, 256>>>(x, wgt);
    finalize_kernel<<<1, 256>>>(gamma, beta);
    conv_kernel<<<2048, 128>>>(x, wgt, (float*)d_out);
}

// round 6
// speedup vs baseline: 2.4870x; 1.1991x over previous
#include <cuda_runtime.h>

// Problem constants
#define Bn   2
#define Cc   64
#define Oo   64
#define Gg   16
#define Ee   128
#define Tin  512
#define Wk   7
#define Dd   4
#define Tout 256
#define FO   64
#define PER  264   // padded de-interleaved row length (floats)

// Per-block BN-stat partials: [o][j], j = b*16 + d*4 + fq  (32 slots)
__device__ float  g_part1[Oo][32];
__device__ float  g_part2[Oo][32];
__device__ float2 g_ab[Oo];           // {a, bias56}

// ---------------------------------------------------------------------------
// Stats kernel: grid (b, c, fq) = 2*64*4 = 512 blocks, 256 threads.
// Each 8-lane group owns one row f; lane sl loads float4 indices sl+8k
// (k=0..15, two batches of 8 -> MLP 8). 3-level butterfly within the group,
// boundary values via targeted shfl, per-lane (oc=sl<4) weight dot, 2-level
// cross-group fold, 4 smem atomics per warp.
// ---------------------------------------------------------------------------
__global__ __launch_bounds__(256) void stats_kernel(const float* __restrict__ x,
                                                    const float* __restrict__ wgt) {
    __shared__ float s_p1[4], s_p2[4];

    const int bid  = blockIdx.x;
    const int b    = bid >> 8;
    const int c    = (bid >> 2) & 63;
    const int fq   = bid & 3;
    const int tid  = threadIdx.x;
    const int warp = tid >> 5;
    const int lane = tid & 31;
    const int sl   = lane & 7;
    const int gidx = lane >> 3;
    const int f    = fq * 32 + warp * 4 + gidx;

    if (tid < 4) { s_p1[tid] = 0.f; s_p2[tid] = 0.f; }
    __syncthreads();

    const float4* row = reinterpret_cast<const float4*>(
        &x[((b * Cc + c) * Ee + f) * Tin]);

    float se = 0.f, so = 0.f, se2 = 0.f, so2 = 0.f;
    float4 vfirst, vlast;

    // Batch A: k = 0..7
    {
        float4 v[8];
#pragma unroll
        for (int k = 0; k < 8; k++) v[k] = row[sl + 8 * k];
        vfirst = v[0];
#pragma unroll
        for (int k = 0; k < 8; k++) {
            float4 q = v[k];
            se += q.x + q.z;  so += q.y + q.w;
            se2 = fmaf(q.x, q.x, se2); se2 = fmaf(q.z, q.z, se2);
            so2 = fmaf(q.y, q.y, so2); so2 = fmaf(q.w, q.w, so2);
        }
    }
    // Batch B: k = 8..15
    {
        float4 v[8];
#pragma unroll
        for (int k = 0; k < 8; k++) v[k] = row[sl + 8 * (k + 8)];
        vlast = v[7];
#pragma unroll
        for (int k = 0; k < 8; k++) {
            float4 q = v[k];
            se += q.x + q.z;  so += q.y + q.w;
            se2 = fmaf(q.x, q.x, se2); se2 = fmaf(q.z, q.z, se2);
            so2 = fmaf(q.y, q.y, so2); so2 = fmaf(q.w, q.w, so2);
        }
    }

    const unsigned FULL = 0xffffffffu;
    const int base = lane & ~7;
    // boundary values: x0,x1 from group's lane sl=0 (float4 idx 0);
    // x509..x511 from lane sl=7 (float4 idx 127)
    float x0   = __shfl_sync(FULL, vfirst.x, base);
    float x1   = __shfl_sync(FULL, vfirst.y, base);
    float x509 = __shfl_sync(FULL, vlast.y,  base + 7);
    float x510 = __shfl_sync(FULL, vlast.z,  base + 7);
    float x511 = __shfl_sync(FULL, vlast.w,  base + 7);

#pragma unroll
    for (int off = 1; off < 8; off <<= 1) {
        se  += __shfl_xor_sync(FULL, se,  off);
        so  += __shfl_xor_sync(FULL, so,  off);
        se2 += __shfl_xor_sync(FULL, se2, off);
        so2 += __shfl_xor_sync(FULL, so2, off);
    }

    float c1 = 0.f, c2 = 0.f;
    if (sl < 4) {
        float s1[7], s2[7];
        s1[0] = so - x509 - x511;  s2[0] = so2 - x509 * x509 - x511 * x511;
        s1[1] = se - x510;         s2[1] = se2 - x510 * x510;
        s1[2] = so - x511;         s2[2] = so2 - x511 * x511;
        s1[3] = se;                s2[3] = se2;
        s1[4] = so;                s2[4] = so2;
        s1[5] = se - x0;           s2[5] = se2 - x0 * x0;
        s1[6] = so - x1;           s2[6] = so2 - x1 * x1;

        const int g = c >> 2, d = c & 3;
        const int o = g * 4 + sl;
        const float* wp = &wgt[((o * Dd + d) * Ee + f) * Wk];
#pragma unroll
        for (int w = 0; w < 7; w++) {
            float wv = wp[w];
            c1 = fmaf(wv, s1[w], c1);
            c2 = fmaf(wv * wv, s2[w], c2);
        }
    }
    // fold the 4 groups of the warp (lanes sl>=4 contribute zeros)
    c1 += __shfl_xor_sync(FULL, c1, 8);
    c1 += __shfl_xor_sync(FULL, c1, 16);
    c2 += __shfl_xor_sync(FULL, c2, 8);
    c2 += __shfl_xor_sync(FULL, c2, 16);
    if (lane < 4) {
        atomicAdd(&s_p1[lane], c1);
        atomicAdd(&s_p2[lane], c2);
    }
    __syncthreads();
    if (tid < 4) {
        const int g = c >> 2, d = c & 3;
        const int j = b * 16 + d * 4 + fq;
        g_part1[g * 4 + tid][j] = s_p1[tid];
        g_part2[g * 4 + tid][j] = s_p2[tid];
    }
}

// ---------------------------------------------------------------------------
// Finalize: 1 block, 64 threads; thread o reduces its 32 partials, writes g_ab.
// ---------------------------------------------------------------------------
__global__ __launch_bounds__(64) void finalize_kernel(const float* __restrict__ gamma,
                                                      const float* __restrict__ beta) {
    const int o = threadIdx.x;
    const float4* p1v = reinterpret_cast<const float4*>(g_part1[o]);
    const float4* p2v = reinterpret_cast<const float4*>(g_part2[o]);
    float p1 = 0.f, p2 = 0.f;
#pragma unroll
    for (int k = 0; k < 8; k++) {
        float4 a = p1v[k], b = p2v[k];
        p1 += (a.x + a.y) + (a.z + a.w);
        p2 += (b.x + b.y) + (b.z + b.w);
    }
    const float M = 1835008.f;   // B*D*E*t*W
    float mean = p1 / M;
    float var  = p2 / M - mean * mean;
    float a    = gamma[o] * rsqrtf(var + 1e-5f);
    g_ab[o] = make_float2(a, 56.f * (beta[o] - mean * a));
}

// ---------------------------------------------------------------------------
// Fused conv + BN-affine + LeakyReLU (validated R5 core). Block = (b, g, fo),
// 2048 blocks, 128 threads.
// ---------------------------------------------------------------------------
__global__ __launch_bounds__(128) void conv_kernel(const float* __restrict__ x,
                                                   const float* __restrict__ wgt,
                                                   float* __restrict__ out) {
    __shared__ alignas(16) float pe[8][PER];
    __shared__ alignas(16) float pos[8][PER];
    __shared__ alignas(16) float ws[8][4][8];   // [w0..w6, 0]

    const int bid  = blockIdx.x;
    const int b    = bid >> 10;
    const int g    = (bid >> 6) & 15;
    const int fo   = bid & 63;
    const int tid  = threadIdx.x;
    const int lane = tid & 31;
    const int warp = tid >> 5;
    const int oc   = lane & 3;
    const int tc   = warp * 8 + (lane >> 2);   // 0..31; outputs t = 8tc..8tc+7

    const float2 ab = g_ab[g * 4 + oc];

    // zero boundary slots {0,1,258..263} of each pe/pos row
    {
        int r  = tid >> 4;
        int s  = tid & 15;
        int ss = s & 7;
        int idx = (ss < 2) ? ss : (256 + ss);
        if (s < 8) pe[r][idx] = 0.f; else pos[r][idx] = 0.f;
    }

    // de-interleaving fill
#pragma unroll
    for (int k = 0; k < 8; k++) {
        const int c = g * 4 + (k & 3);
        const int f = 2 * fo + (k >> 2);
        float4 v = reinterpret_cast<const float4*>(
            &x[((b * Cc + c) * Ee + f) * Tin])[tid];
        *reinterpret_cast<float2*>(&pe[k][2 * tid + 2])  = make_float2(v.y, v.w);
        *reinterpret_cast<float2*>(&pos[k][2 * tid + 2]) = make_float2(v.x, v.z);
    }

    // weights
#pragma unroll
    for (int m = 0; m < 2; m++) {
        int j  = tid + 128 * m;
        int r  = j >> 5;
        int o2 = (j >> 3) & 3;
        int w  = j & 7;
        int d  = r & 3;
        int f2 = r >> 2;
        ws[r][o2][w] = (w < 7)
            ? wgt[(((g * 4 + o2) * Dd + d) * Ee + (2 * fo + f2)) * Wk + w] : 0.f;
    }
    __syncthreads();

    float acc[8];
#pragma unroll
    for (int j = 0; j < 8; j++) acc[j] = 0.f;

#pragma unroll
    for (int r = 0; r < 8; r++) {
        const float4* pe4  = reinterpret_cast<const float4*>(pe[r]);
        const float4* pos4 = reinterpret_cast<const float4*>(pos[r]);
        float E[12], S[12];
        *reinterpret_cast<float4*>(&E[0]) = pe4[2 * tc];
        *reinterpret_cast<float4*>(&E[4]) = pe4[2 * tc + 1];
        *reinterpret_cast<float4*>(&E[8]) = pe4[2 * tc + 2];
        *reinterpret_cast<float4*>(&S[0]) = pos4[2 * tc];
        *reinterpret_cast<float4*>(&S[4]) = pos4[2 * tc + 1];
        *reinterpret_cast<float4*>(&S[8]) = pos4[2 * tc + 2];
        float4 wA = *reinterpret_cast<const float4*>(&ws[r][oc][0]);
        float4 wB = *reinterpret_cast<const float4*>(&ws[r][oc][4]);
#pragma unroll
        for (int j = 0; j < 8; j++) {
            acc[j] = fmaf(wA.x, E[j],     acc[j]);
            acc[j] = fmaf(wA.y, S[j + 1], acc[j]);
            acc[j] = fmaf(wA.z, E[j + 1], acc[j]);
            acc[j] = fmaf(wA.w, S[j + 2], acc[j]);
            acc[j] = fmaf(wB.x, E[j + 2], acc[j]);
            acc[j] = fmaf(wB.y, S[j + 3], acc[j]);
            acc[j] = fmaf(wB.z, E[j + 3], acc[j]);
        }
    }

    {
        float r0[8];
#pragma unroll
        for (int j = 0; j < 8; j++) {
            float v = fmaf(ab.x, acc[j], ab.y);
            r0[j] = (v >= 0.f) ? v : 0.01f * v;
        }
        int ob = ((b * Oo + g * 4 + oc) * FO + fo) * Tout + 8 * tc;
        *reinterpret_cast<float4*>(&out[ob])     = make_float4(r0[0], r0[1], r0[2], r0[3]);
        *reinterpret_cast<float4*>(&out[ob + 4]) = make_float4(r0[4], r0[5], r0[6], r0[7]);
    }
}

extern "C" void kernel_launch(void* const* d_in, const int* in_sizes, int n_in,
                              void* d_out, int out_size) {
    const float* x     = (const float*)d_in[0];
    const float* wgt   = (const float*)d_in[1];
    const float* gamma = (const float*)d_in[2];
    const float* beta  = (const float*)d_in[3];

    stats_kernel<<<512, 256>>>(x, wgt);
    finalize_kernel<<<1, 64>>>(gamma, beta);
    conv_kernel<<<2048, 128>>>(x, wgt, (float*)d_out);
}